// round 1
// baseline (speedup 1.0000x reference)
#include <cuda_runtime.h>
#include <float.h>

// T is 8192 in the dataset; scratch sized for it.
#define MAXT 8192

// Scratch: projections (graph-capturable, no allocs).
__device__ float2 g_Qp[MAXT], g_Kp[MAXT], g_Qs[MAXT], g_Ks[MAXT];
__device__ float  g_Vop[MAXT], g_Varg[MAXT], g_Vstk[MAXT];

// ---------------------------------------------------------------------------
// Kernel 1: per-row projections. 9 length-D dot products per row.
// Weights staged in shared memory (396 floats), one thread per row.
// ---------------------------------------------------------------------------
__global__ void proj_kernel(const float* __restrict__ emb,
                            const float* __restrict__ wqp,
                            const float* __restrict__ wkp,
                            const float* __restrict__ wvop,
                            const float* __restrict__ wvarg,
                            const float* __restrict__ wqs,
                            const float* __restrict__ wks,
                            const float* __restrict__ wvs,
                            int T, int D) {
    extern __shared__ float sw[];  // 11*D floats
    int tid = threadIdx.x;
    for (int k = tid; k < 2 * D; k += blockDim.x) {
        sw[k]         = wqp[k];
        sw[2 * D + k] = wkp[k];
        sw[4 * D + k] = wqs[k];
        sw[6 * D + k] = wks[k];
    }
    for (int k = tid; k < D; k += blockDim.x) {
        sw[8 * D + k]  = wvop[k];
        sw[9 * D + k]  = wvarg[k];
        sw[10 * D + k] = wvs[k];
    }
    __syncthreads();

    int i = blockIdx.x * blockDim.x + tid;
    if (i >= T) return;
    const float* e = emb + (size_t)i * D;

    float a0 = 0.f, a1 = 0.f, a2 = 0.f, a3 = 0.f, a4 = 0.f, a5 = 0.f;
    float a6 = 0.f, a7 = 0.f, a8 = 0.f, a9 = 0.f, a10 = 0.f;
    for (int d = 0; d < D; d++) {
        float ev = e[d];
        a0  = fmaf(ev, sw[d],          a0);   // Q_prog.x
        a1  = fmaf(ev, sw[D + d],      a1);   // Q_prog.y
        a2  = fmaf(ev, sw[2 * D + d],  a2);   // K_prog.x
        a3  = fmaf(ev, sw[3 * D + d],  a3);   // K_prog.y
        a4  = fmaf(ev, sw[4 * D + d],  a4);   // Q_stack.x
        a5  = fmaf(ev, sw[5 * D + d],  a5);   // Q_stack.y
        a6  = fmaf(ev, sw[6 * D + d],  a6);   // K_stack.x
        a7  = fmaf(ev, sw[7 * D + d],  a7);   // K_stack.y
        a8  = fmaf(ev, sw[8 * D + d],  a8);   // V_op
        a9  = fmaf(ev, sw[9 * D + d],  a9);   // V_arg
        a10 = fmaf(ev, sw[10 * D + d], a10);  // V_stack
    }
    g_Qp[i]  = make_float2(a0, a1);
    g_Kp[i]  = make_float2(a2, a3);
    g_Qs[i]  = make_float2(a4, a5);
    g_Ks[i]  = make_float2(a6, a7);
    g_Vop[i] = a8;
    g_Varg[i]= a9;
    g_Vstk[i]= a10;
}

// ---------------------------------------------------------------------------
// Kernel 2: brute-force argmax over keys (both heads fused) + gather.
// One block handles QB queries; keys stream through L1/L2 (128 KB total
// key data => fully cache-resident). Tie semantics match jnp.argmax
// (first index of the max): strict '>' within an increasing-j scan,
// (larger value, else smaller index) across lanes/warps.
// ---------------------------------------------------------------------------
#define NT 256
#define QB 4

__device__ __forceinline__ void red_pair(float& v, int& ix, float ov, int oi) {
    if (ov > v || (ov == v && oi < ix)) { v = ov; ix = oi; }
}

__global__ __launch_bounds__(NT) void argmax_kernel(float* __restrict__ out, int T) {
    const int tid   = threadIdx.x;
    const int qbase = blockIdx.x * QB;

    float2 qp[QB], qs[QB];
#pragma unroll
    for (int qq = 0; qq < QB; qq++) {
        qp[qq] = g_Qp[qbase + qq];
        qs[qq] = g_Qs[qbase + qq];
    }

    float bvP[QB], bvS[QB];
    int   biP[QB], biS[QB];
#pragma unroll
    for (int qq = 0; qq < QB; qq++) {
        bvP[qq] = -FLT_MAX; bvS[qq] = -FLT_MAX;
        biP[qq] = 0x7fffffff; biS[qq] = 0x7fffffff;
    }

    for (int j = tid; j < T; j += NT) {
        float2 kp = g_Kp[j];
        float2 ks = g_Ks[j];
#pragma unroll
        for (int qq = 0; qq < QB; qq++) {
            float sp = fmaf(qp[qq].x, kp.x, qp[qq].y * kp.y);
            if (sp > bvP[qq]) { bvP[qq] = sp; biP[qq] = j; }
            float ss = fmaf(qs[qq].x, ks.x, qs[qq].y * ks.y);
            if (ss > bvS[qq]) { bvS[qq] = ss; biS[qq] = j; }
        }
    }

    // ---- reduction ----
    const int NW = NT / 32;
    __shared__ float svP[QB][NW], svS[QB][NW];
    __shared__ int   siP[QB][NW], siS[QB][NW];
    const int lane = tid & 31, wid = tid >> 5;

#pragma unroll
    for (int qq = 0; qq < QB; qq++) {
        float v = bvP[qq]; int ix = biP[qq];
#pragma unroll
        for (int off = 16; off; off >>= 1) {
            float ov = __shfl_down_sync(0xffffffffu, v, off);
            int   oi = __shfl_down_sync(0xffffffffu, ix, off);
            red_pair(v, ix, ov, oi);
        }
        if (lane == 0) { svP[qq][wid] = v; siP[qq][wid] = ix; }

        v = bvS[qq]; ix = biS[qq];
#pragma unroll
        for (int off = 16; off; off >>= 1) {
            float ov = __shfl_down_sync(0xffffffffu, v, off);
            int   oi = __shfl_down_sync(0xffffffffu, ix, off);
            red_pair(v, ix, ov, oi);
        }
        if (lane == 0) { svS[qq][wid] = v; siS[qq][wid] = ix; }
    }
    __syncthreads();

    if (wid == 0) {
#pragma unroll
        for (int qq = 0; qq < QB; qq++) {
            // program head
            float v  = (lane < NW) ? svP[qq][lane] : -FLT_MAX;
            int   ix = (lane < NW) ? siP[qq][lane] : 0x7fffffff;
#pragma unroll
            for (int off = NW / 2; off; off >>= 1) {
                float ov = __shfl_down_sync(0xffffffffu, v, off);
                int   oi = __shfl_down_sync(0xffffffffu, ix, off);
                red_pair(v, ix, ov, oi);
            }
            if (lane == 0) {
                out[qbase + qq]     = g_Vop[ix];
                out[T + qbase + qq] = g_Varg[ix];
            }
            // stack head
            v  = (lane < NW) ? svS[qq][lane] : -FLT_MAX;
            ix = (lane < NW) ? siS[qq][lane] : 0x7fffffff;
#pragma unroll
            for (int off = NW / 2; off; off >>= 1) {
                float ov = __shfl_down_sync(0xffffffffu, v, off);
                int   oi = __shfl_down_sync(0xffffffffu, ix, off);
                red_pair(v, ix, ov, oi);
            }
            if (lane == 0) {
                out[2 * T + qbase + qq] = g_Vstk[ix];
            }
        }
    }
}

extern "C" void kernel_launch(void* const* d_in, const int* in_sizes, int n_in,
                              void* d_out, int out_size) {
    const float* emb   = (const float*)d_in[0];
    const float* wqp   = (const float*)d_in[1];
    const float* wkp   = (const float*)d_in[2];
    const float* wvop  = (const float*)d_in[3];
    const float* wvarg = (const float*)d_in[4];
    const float* wqs   = (const float*)d_in[5];
    const float* wks   = (const float*)d_in[6];
    const float* wvs   = (const float*)d_in[7];
    float* out = (float*)d_out;

    const int D = in_sizes[1] / 2;          // WQ_prog is (2, D)
    const int T = in_sizes[0] / D;          // embeddings is (T, D)

    int pb = (T + 255) / 256;
    size_t smem = (size_t)(11 * D) * sizeof(float);
    proj_kernel<<<pb, 256, smem>>>(emb, wqp, wkp, wvop, wvarg, wqs, wks, wvs, T, D);

    argmax_kernel<<<T / QB, NT>>>(out, T);
}

// round 2
// speedup vs baseline: 1.2262x; 1.2262x over previous
#include <cuda_runtime.h>
#include <float.h>

#define MAXT 8192

// Packed scratch (graph-capturable, no allocs).
//   g_QQ[i] = { pack(Qprog.x, Qstack.x), pack(Qprog.y, Qstack.y) }
//   g_KK[j] = { pack(Kprog.x, Kstack.x), pack(Kprog.y, Kstack.y) }
__device__ ulonglong2 g_QQ[MAXT];
__device__ ulonglong2 g_KK[MAXT];
__device__ float g_Vop[MAXT], g_Varg[MAXT], g_Vstk[MAXT];

__device__ __forceinline__ unsigned long long packf2(float lo, float hi) {
    return ((unsigned long long)__float_as_uint(hi) << 32) | (unsigned long long)__float_as_uint(lo);
}
__device__ __forceinline__ float lo32(unsigned long long v) { return __uint_as_float((unsigned)v); }
__device__ __forceinline__ float hi32(unsigned long long v) { return __uint_as_float((unsigned)(v >> 32)); }

// sm_103a packed fp32 pair math (not emitted by ptxas from C++; PTX only).
__device__ __forceinline__ unsigned long long mul2(unsigned long long a, unsigned long long b) {
    unsigned long long r;
    asm("mul.rn.f32x2 %0, %1, %2;" : "=l"(r) : "l"(a), "l"(b));
    return r;
}
__device__ __forceinline__ unsigned long long fma2(unsigned long long a, unsigned long long b, unsigned long long c) {
    unsigned long long r;
    asm("fma.rn.f32x2 %0, %1, %2, %3;" : "=l"(r) : "l"(a), "l"(b), "l"(c));
    return r;
}

// ---------------------------------------------------------------------------
// Kernel 1: projections with coalesced staging through shared memory.
// Block of PT threads handles PT rows. Row data staged coalesced into padded
// smem (stride D+1 => conflict-free readback), weights broadcast from smem.
// ---------------------------------------------------------------------------
#define PT 128

__global__ void proj_kernel(const float* __restrict__ emb,
                            const float* __restrict__ wqp,
                            const float* __restrict__ wkp,
                            const float* __restrict__ wvop,
                            const float* __restrict__ wvarg,
                            const float* __restrict__ wqs,
                            const float* __restrict__ wks,
                            const float* __restrict__ wvs,
                            int T, int D) {
    extern __shared__ float sm[];       // [11*D weights][PT*(D+1) rows]
    float* sw = sm;
    float* se = sm + 11 * D;
    const int tid = threadIdx.x;
    const int DP = D + 1;

    for (int k = tid; k < 2 * D; k += PT) {
        sw[k]         = wqp[k];
        sw[2 * D + k] = wkp[k];
        sw[4 * D + k] = wqs[k];
        sw[6 * D + k] = wks[k];
    }
    for (int k = tid; k < D; k += PT) {
        sw[8 * D + k]  = wvop[k];
        sw[9 * D + k]  = wvarg[k];
        sw[10 * D + k] = wvs[k];
    }

    const int base = blockIdx.x * PT;
    const int rows = min(PT, T - base);
    for (int idx = tid; idx < rows * D; idx += PT) {
        int r = idx / D;
        int d = idx - r * D;
        se[r * DP + d] = emb[(size_t)base * D + idx];
    }
    __syncthreads();

    const int i = base + tid;
    if (i >= T) return;

    float a0 = 0.f, a1 = 0.f, a2 = 0.f, a3 = 0.f, a4 = 0.f, a5 = 0.f;
    float a6 = 0.f, a7 = 0.f, a8 = 0.f, a9 = 0.f, a10 = 0.f;
    const float* row = se + tid * DP;
    for (int d = 0; d < D; d++) {
        float ev = row[d];
        a0  = fmaf(ev, sw[d],          a0);   // Qp.x
        a1  = fmaf(ev, sw[D + d],      a1);   // Qp.y
        a2  = fmaf(ev, sw[2 * D + d],  a2);   // Kp.x
        a3  = fmaf(ev, sw[3 * D + d],  a3);   // Kp.y
        a4  = fmaf(ev, sw[4 * D + d],  a4);   // Qs.x
        a5  = fmaf(ev, sw[5 * D + d],  a5);   // Qs.y
        a6  = fmaf(ev, sw[6 * D + d],  a6);   // Ks.x
        a7  = fmaf(ev, sw[7 * D + d],  a7);   // Ks.y
        a8  = fmaf(ev, sw[8 * D + d],  a8);   // V_op
        a9  = fmaf(ev, sw[9 * D + d],  a9);   // V_arg
        a10 = fmaf(ev, sw[10 * D + d], a10);  // V_stack
    }
    g_QQ[i] = make_ulonglong2(packf2(a0, a4), packf2(a1, a5));
    g_KK[i] = make_ulonglong2(packf2(a2, a6), packf2(a3, a7));
    g_Vop[i]  = a8;
    g_Varg[i] = a9;
    g_Vstk[i] = a10;
}

// ---------------------------------------------------------------------------
// Kernel 2: fused argmax, fmax-only hot loop (f32x2 packed), then sparse
// rescan for the first index. QB queries per block, both heads per lane-pair.
// ---------------------------------------------------------------------------
#define NT 256
#define QB 4
#define NW (NT / 32)

__global__ __launch_bounds__(NT) void argmax_kernel(float* __restrict__ out, int T) {
    __shared__ float sred[2 * QB][NW];
    __shared__ float sG[2 * QB];
    __shared__ int   sIdx[2 * QB];

    const int tid  = threadIdx.x;
    const int lane = tid & 31;
    const int wid  = tid >> 5;
    const int qbase = blockIdx.x * QB;

    if (tid < 2 * QB) sIdx[tid] = 0x7fffffff;

    unsigned long long qa[QB], qb[QB];
#pragma unroll
    for (int qq = 0; qq < QB; qq++) {
        ulonglong2 q = g_QQ[qbase + qq];
        qa[qq] = q.x;
        qb[qq] = q.y;
    }

    float mP[QB], mS[QB];
#pragma unroll
    for (int qq = 0; qq < QB; qq++) { mP[qq] = -FLT_MAX; mS[qq] = -FLT_MAX; }

    // ---- pass A: max only (no index tracking) ----
#pragma unroll 4
    for (int j = tid; j < T; j += NT) {
        ulonglong2 kk = g_KK[j];
#pragma unroll
        for (int qq = 0; qq < QB; qq++) {
            unsigned long long s = fma2(qa[qq], kk.x, mul2(qb[qq], kk.y));
            mP[qq] = fmaxf(mP[qq], lo32(s));   // prog head
            mS[qq] = fmaxf(mS[qq], hi32(s));   // stack head
        }
    }

    // ---- block max reduction (8 streams) ----
    float loc[2 * QB];
#pragma unroll
    for (int qq = 0; qq < QB; qq++) { loc[2 * qq] = mP[qq]; loc[2 * qq + 1] = mS[qq]; }
#pragma unroll
    for (int s = 0; s < 2 * QB; s++) {
        float v = loc[s];
#pragma unroll
        for (int off = 16; off; off >>= 1)
            v = fmaxf(v, __shfl_xor_sync(0xffffffffu, v, off));
        if (lane == 0) sred[s][wid] = v;
    }
    __syncthreads();
    if (tid < 2 * QB) {
        float v = sred[tid][0];
#pragma unroll
        for (int w = 1; w < NW; w++) v = fmaxf(v, sred[tid][w]);
        sG[tid] = v;
    }
    __syncthreads();

    // ---- sparse rescan: only threads whose local max hit the global max ----
#pragma unroll
    for (int qq = 0; qq < QB; qq++) {
        const float gP = sG[2 * qq];
        const float gS = sG[2 * qq + 1];
        const bool needP = (mP[qq] == gP);
        const bool needS = (mS[qq] == gS);
        if (needP || needS) {
            const float qpx = lo32(qa[qq]), qsx = hi32(qa[qq]);
            const float qpy = lo32(qb[qq]), qsy = hi32(qb[qq]);
            int bjP = 0x7fffffff, bjS = 0x7fffffff;
            for (int j = tid; j < T; j += NT) {
                ulonglong2 kk = g_KK[j];
                float kpx = lo32(kk.x), ksx = hi32(kk.x);
                float kpy = lo32(kk.y), ksy = hi32(kk.y);
                // bit-identical to the f32x2 lanes: mul.rn then fma.rn
                float sp = fmaf(qpx, kpx, __fmul_rn(qpy, kpy));
                float ss = fmaf(qsx, ksx, __fmul_rn(qsy, ksy));
                if (needP && sp == gP && j < bjP) bjP = j;
                if (needS && ss == gS && j < bjS) bjS = j;
            }
            if (bjP != 0x7fffffff) atomicMin(&sIdx[2 * qq], bjP);
            if (bjS != 0x7fffffff) atomicMin(&sIdx[2 * qq + 1], bjS);
        }
    }
    __syncthreads();

    // ---- gather ----
    if (tid < QB) {
        int iP = sIdx[2 * tid];
        int iS = sIdx[2 * tid + 1];
        out[qbase + tid]         = g_Vop[iP];
        out[T + qbase + tid]     = g_Varg[iP];
        out[2 * T + qbase + tid] = g_Vstk[iS];
    }
}

extern "C" void kernel_launch(void* const* d_in, const int* in_sizes, int n_in,
                              void* d_out, int out_size) {
    const float* emb   = (const float*)d_in[0];
    const float* wqp   = (const float*)d_in[1];
    const float* wkp   = (const float*)d_in[2];
    const float* wvop  = (const float*)d_in[3];
    const float* wvarg = (const float*)d_in[4];
    const float* wqs   = (const float*)d_in[5];
    const float* wks   = (const float*)d_in[6];
    const float* wvs   = (const float*)d_in[7];
    float* out = (float*)d_out;

    const int D = in_sizes[1] / 2;   // WQ_prog is (2, D)
    const int T = in_sizes[0] / D;   // embeddings is (T, D)

    const int pb = (T + PT - 1) / PT;
    const size_t smem = (size_t)(11 * D + PT * (D + 1)) * sizeof(float);
    proj_kernel<<<pb, PT, smem>>>(emb, wqp, wkp, wvop, wvarg, wqs, wks, wvs, T, D);

    argmax_kernel<<<T / QB, NT>>>(out, T);
}

// round 3
// speedup vs baseline: 1.4728x; 1.2011x over previous
#include <cuda_runtime.h>
#include <float.h>
#include <math.h>

#define MAXT 8192
#define NB   256          // direction bins
#define CAP  256          // max candidates per bin (Gaussian data: expect ~2)

// Packed scratch (graph-capturable, no allocs, no cross-launch state).
//   g_QQ[i] = { pack(Qprog.x, Qstack.x), pack(Qprog.y, Qstack.y) }
//   g_KK[j] = { pack(Kprog.x, Kstack.x), pack(Kprog.y, Kstack.y) }
__device__ ulonglong2 g_QQ[MAXT], g_KK[MAXT];
__device__ float g_Vop[MAXT], g_Varg[MAXT], g_Vstk[MAXT];
__device__ int g_candP[NB * CAP], g_candS[NB * CAP];
__device__ int g_cntP[NB], g_cntS[NB];

__device__ __forceinline__ unsigned long long packf2(float lo, float hi) {
    return ((unsigned long long)__float_as_uint(hi) << 32) | (unsigned long long)__float_as_uint(lo);
}
__device__ __forceinline__ float lo32(unsigned long long v) { return __uint_as_float((unsigned)v); }
__device__ __forceinline__ float hi32(unsigned long long v) { return __uint_as_float((unsigned)(v >> 32)); }

// sm_103a packed fp32 pair math (PTX-only; ptxas won't auto-fuse).
__device__ __forceinline__ unsigned long long mul2(unsigned long long a, unsigned long long b) {
    unsigned long long r;
    asm("mul.rn.f32x2 %0, %1, %2;" : "=l"(r) : "l"(a), "l"(b));
    return r;
}
__device__ __forceinline__ unsigned long long fma2(unsigned long long a, unsigned long long b, unsigned long long c) {
    unsigned long long r;
    asm("fma.rn.f32x2 %0, %1, %2, %3;" : "=l"(r) : "l"(a), "l"(b), "l"(c));
    return r;
}

// ---------------------------------------------------------------------------
// Kernel 1: projections. 4 threads per row (split over D), shfl reduction.
// Coalesced staging of rows into padded smem; weights broadcast from smem.
// ---------------------------------------------------------------------------
#define PR  64    // rows per block
#define PTH 256   // threads per block (= PR * 4)

__global__ __launch_bounds__(PTH) void proj_kernel(
        const float* __restrict__ emb,
        const float* __restrict__ wqp, const float* __restrict__ wkp,
        const float* __restrict__ wvop, const float* __restrict__ wvarg,
        const float* __restrict__ wqs, const float* __restrict__ wks,
        const float* __restrict__ wvs, int T, int D) {
    extern __shared__ float sm[];      // [11*D weights][PR*(D+1) rows]
    float* sw = sm;
    float* se = sm + 11 * D;
    const int tid = threadIdx.x;
    const int DP = D + 1;

    // weight layout c: 0=Qp.x 1=Qp.y 2=Kp.x 3=Kp.y 4=Qs.x 5=Qs.y 6=Ks.x 7=Ks.y 8=Vop 9=Varg 10=Vstk
    for (int k = tid; k < 2 * D; k += PTH) {
        sw[k]         = wqp[k];
        sw[2 * D + k] = wkp[k];
        sw[4 * D + k] = wqs[k];
        sw[6 * D + k] = wks[k];
    }
    for (int k = tid; k < D; k += PTH) {
        sw[8 * D + k]  = wvop[k];
        sw[9 * D + k]  = wvarg[k];
        sw[10 * D + k] = wvs[k];
    }

    const int base = blockIdx.x * PR;
    const int rows = min(PR, T - base);
    for (int idx = tid; idx < rows * D; idx += PTH) {
        int r = idx / D, d = idx - r * D;
        se[r * DP + d] = emb[(size_t)base * D + idx];
    }
    __syncthreads();

    const int row = tid >> 2, part = tid & 3;
    if (row >= rows) return;
    const int qd = D >> 2;
    const int d0 = part * qd;
    const int d1 = (part == 3) ? D : d0 + qd;

    float a[11];
#pragma unroll
    for (int c = 0; c < 11; c++) a[c] = 0.f;
    const float* r0 = se + row * DP;
    for (int d = d0; d < d1; d++) {
        float ev = r0[d];
#pragma unroll
        for (int c = 0; c < 11; c++) a[c] = fmaf(ev, sw[c * D + d], a[c]);
    }
#pragma unroll
    for (int c = 0; c < 11; c++) {
        a[c] += __shfl_down_sync(0xffffffffu, a[c], 1);
        a[c] += __shfl_down_sync(0xffffffffu, a[c], 2);
    }
    if (part == 0) {
        int i = base + row;
        g_QQ[i] = make_ulonglong2(packf2(a[0], a[4]), packf2(a[1], a[5]));
        g_KK[i] = make_ulonglong2(packf2(a[2], a[6]), packf2(a[3], a[7]));
        g_Vop[i] = a[8]; g_Varg[i] = a[9]; g_Vstk[i] = a[10];
    }
}

// ---------------------------------------------------------------------------
// Kernel 2: per-bin candidate build. One block per direction bin.
// Pass 1: max score + max |k|^2 along bin-center direction (both heads via
// f32x2). Pass 2: collect all keys within the conservative margin
// 1.25 * Kmax * Delta, which provably (exact math + fp slack) contains the
// argmax key for every query direction that maps to this bin.
// ---------------------------------------------------------------------------
#define BTH 256

__global__ __launch_bounds__(BTH) void build_kernel(int T) {
    __shared__ float red[4][BTH / 32];
    __shared__ float sTP, sTS;
    __shared__ int cP, cS;

    const int b = blockIdx.x;
    const int tid = threadIdx.x, lane = tid & 31, w = tid >> 5;
    const float DLT = 6.2831853071795865f / NB;
    const float th = -3.14159265358979f + (b + 0.5f) * DLT;
    const float ux = cosf(th), uy = sinf(th);
    const unsigned long long ua = packf2(ux, ux), ub = packf2(uy, uy);

    float v[4] = {-FLT_MAX, -FLT_MAX, 0.f, 0.f};  // maxP, maxS, n2P, n2S
    for (int j = tid; j < T; j += BTH) {
        ulonglong2 kk = g_KK[j];
        unsigned long long s  = fma2(ua, kk.x, mul2(ub, kk.y));
        unsigned long long n2 = fma2(kk.x, kk.x, mul2(kk.y, kk.y));
        v[0] = fmaxf(v[0], lo32(s));  v[1] = fmaxf(v[1], hi32(s));
        v[2] = fmaxf(v[2], lo32(n2)); v[3] = fmaxf(v[3], hi32(n2));
    }
#pragma unroll
    for (int c = 0; c < 4; c++) {
#pragma unroll
        for (int off = 16; off; off >>= 1)
            v[c] = fmaxf(v[c], __shfl_xor_sync(0xffffffffu, v[c], off));
        if (lane == 0) red[c][w] = v[c];
    }
    if (tid == 0) { cP = 0; cS = 0; }
    __syncthreads();
    if (tid == 0) {
        float MP = red[0][0], MS = red[1][0], NP = red[2][0], NS = red[3][0];
#pragma unroll
        for (int k = 1; k < BTH / 32; k++) {
            MP = fmaxf(MP, red[0][k]); MS = fmaxf(MS, red[1][k]);
            NP = fmaxf(NP, red[2][k]); NS = fmaxf(NS, red[3][k]);
        }
        sTP = MP - 1.25f * sqrtf(NP) * DLT;
        sTS = MS - 1.25f * sqrtf(NS) * DLT;
    }
    __syncthreads();
    const float tP = sTP, tS = sTS;

    for (int j = tid; j < T; j += BTH) {
        ulonglong2 kk = g_KK[j];
        unsigned long long s = fma2(ua, kk.x, mul2(ub, kk.y));
        if (lo32(s) >= tP) { int p = atomicAdd(&cP, 1); if (p < CAP) g_candP[b * CAP + p] = j; }
        if (hi32(s) >= tS) { int p = atomicAdd(&cS, 1); if (p < CAP) g_candS[b * CAP + p] = j; }
    }
    __syncthreads();
    if (tid == 0) { g_cntP[b] = min(cP, CAP); g_cntS[b] = min(cS, CAP); }
}

// ---------------------------------------------------------------------------
// Kernel 3: per-query exact argmax over the (tiny) candidate list + gather.
// Candidate order is nondeterministic; the (val,idx) tie-break compare makes
// the result order-independent and matches jnp.argmax first-index semantics.
// ---------------------------------------------------------------------------
__global__ void query_kernel(float* __restrict__ out, int T) {
    const int i = blockIdx.x * blockDim.x + threadIdx.x;
    if (i >= T) return;
    ulonglong2 q = g_QQ[i];
    const float qpx = lo32(q.x), qsx = hi32(q.x);
    const float qpy = lo32(q.y), qsy = hi32(q.y);
    const float SC = NB / 6.2831853071795865f;
    const float PI = 3.14159265358979f;

    int bP = (int)((atan2f(qpy, qpx) + PI) * SC);
    bP = min(max(bP, 0), NB - 1);
    int bS = (int)((atan2f(qsy, qsx) + PI) * SC);
    bS = min(max(bS, 0), NB - 1);

    // program head
    {
        float best = -FLT_MAX; int bi = 0x7fffffff;
        const int n = g_cntP[bP];
        const int* cl = g_candP + bP * CAP;
        for (int t = 0; t < n; t++) {
            int j = cl[t];
            ulonglong2 kk = g_KK[j];
            float s = fmaf(qpx, lo32(kk.x), __fmul_rn(qpy, lo32(kk.y)));
            if (s > best || (s == best && j < bi)) { best = s; bi = j; }
        }
        out[i]     = g_Vop[bi];
        out[T + i] = g_Varg[bi];
    }
    // stack head
    {
        float best = -FLT_MAX; int bi = 0x7fffffff;
        const int n = g_cntS[bS];
        const int* cl = g_candS + bS * CAP;
        for (int t = 0; t < n; t++) {
            int j = cl[t];
            ulonglong2 kk = g_KK[j];
            float s = fmaf(qsx, hi32(kk.x), __fmul_rn(qsy, hi32(kk.y)));
            if (s > best || (s == best && j < bi)) { best = s; bi = j; }
        }
        out[2 * T + i] = g_Vstk[bi];
    }
}

extern "C" void kernel_launch(void* const* d_in, const int* in_sizes, int n_in,
                              void* d_out, int out_size) {
    const float* emb   = (const float*)d_in[0];
    const float* wqp   = (const float*)d_in[1];
    const float* wkp   = (const float*)d_in[2];
    const float* wvop  = (const float*)d_in[3];
    const float* wvarg = (const float*)d_in[4];
    const float* wqs   = (const float*)d_in[5];
    const float* wks   = (const float*)d_in[6];
    const float* wvs   = (const float*)d_in[7];
    float* out = (float*)d_out;

    const int D = in_sizes[1] / 2;   // WQ_prog is (2, D)
    const int T = in_sizes[0] / D;   // embeddings is (T, D)

    const int pb = (T + PR - 1) / PR;
    const size_t smem = (size_t)(11 * D + PR * (D + 1)) * sizeof(float);
    proj_kernel<<<pb, PTH, smem>>>(emb, wqp, wkp, wvop, wvarg, wqs, wks, wvs, T, D);

    build_kernel<<<NB, BTH>>>(T);

    query_kernel<<<(T + 255) / 256, 256>>>(out, T);
}

// round 4
// speedup vs baseline: 2.2889x; 1.5541x over previous
#include <cuda_runtime.h>
#include <float.h>
#include <math.h>

#define MAXT 8192
#define NB   256          // direction bins
#define CAP  256          // max candidates per bin (Gaussian data: expect ~2)

// Packed scratch (graph-capturable, no allocs, no cross-launch state).
//   g_QQ[i] = { pack(Qprog.x, Qstack.x), pack(Qprog.y, Qstack.y) }
//   g_KK[j] = { pack(Kprog.x, Kstack.x), pack(Kprog.y, Kstack.y) }
__device__ ulonglong2 g_QQ[MAXT], g_KK[MAXT];
__device__ float g_Vop[MAXT], g_Varg[MAXT], g_Vstk[MAXT];
__device__ int g_candP[NB * CAP], g_candS[NB * CAP];
__device__ int g_cntP[NB], g_cntS[NB];

__device__ __forceinline__ unsigned long long packf2(float lo, float hi) {
    return ((unsigned long long)__float_as_uint(hi) << 32) | (unsigned long long)__float_as_uint(lo);
}
__device__ __forceinline__ float lo32(unsigned long long v) { return __uint_as_float((unsigned)v); }
__device__ __forceinline__ float hi32(unsigned long long v) { return __uint_as_float((unsigned)(v >> 32)); }

// sm_103a packed fp32 pair math (PTX-only; ptxas won't auto-fuse).
__device__ __forceinline__ unsigned long long mul2(unsigned long long a, unsigned long long b) {
    unsigned long long r;
    asm("mul.rn.f32x2 %0, %1, %2;" : "=l"(r) : "l"(a), "l"(b));
    return r;
}
__device__ __forceinline__ unsigned long long fma2(unsigned long long a, unsigned long long b, unsigned long long c) {
    unsigned long long r;
    asm("fma.rn.f32x2 %0, %1, %2, %3;" : "=l"(r) : "l"(a), "l"(b), "l"(c));
    return r;
}

// ---------------------------------------------------------------------------
// Kernel 1a: projections, specialized for D == 36.
// 32 rows/block, 4 threads/row (9 dims each), float4 staging, full unroll.
// Bank analysis: compute reads at addr row*36 + part*9 + dd; for fixed dd the
// 32 lanes (8 rows x 4 parts) map to 32 distinct banks (4r + 9p mod 32 is a
// bijection) -> conflict-free with no padding; float4 staging stays aligned.
// ---------------------------------------------------------------------------
#define PD  36
#define PR  32
#define PTH 128

__global__ __launch_bounds__(PTH) void proj36_kernel(
        const float* __restrict__ emb,
        const float* __restrict__ wqp, const float* __restrict__ wkp,
        const float* __restrict__ wvop, const float* __restrict__ wvarg,
        const float* __restrict__ wqs, const float* __restrict__ wks,
        const float* __restrict__ wvs, int T) {
    __shared__ float sw[11 * PD];
    __shared__ float se[PR * PD];
    const int tid = threadIdx.x;

    // weight layout c: 0=Qp.x 1=Qp.y 2=Kp.x 3=Kp.y 4=Qs.x 5=Qs.y 6=Ks.x 7=Ks.y 8=Vop 9=Varg 10=Vstk
    for (int k = tid; k < 2 * PD; k += PTH) {
        sw[k]          = wqp[k];
        sw[2 * PD + k] = wkp[k];
        sw[4 * PD + k] = wqs[k];
        sw[6 * PD + k] = wks[k];
    }
    if (tid < PD) {
        sw[8 * PD + tid]  = wvop[tid];
        sw[9 * PD + tid]  = wvarg[tid];
        sw[10 * PD + tid] = wvs[tid];
    }

    const int base = blockIdx.x * PR;
    // stage 32 rows * 36 floats = 288 float4 (block base byte offset is 16B-aligned)
    const float4* emb4 = (const float4*)(emb + (size_t)base * PD);
#pragma unroll
    for (int v = 0; v < (PR * PD / 4) / PTH + 1; v++) {
        int idx = tid + v * PTH;
        if (idx < PR * PD / 4) ((float4*)se)[idx] = emb4[idx];
    }
    __syncthreads();

    const int row = tid >> 2, part = tid & 3;
    const float* r0 = se + row * PD + part * 9;

    float rv[9];
#pragma unroll
    for (int dd = 0; dd < 9; dd++) rv[dd] = r0[dd];

    float a[11];
#pragma unroll
    for (int c = 0; c < 11; c++) a[c] = 0.f;
#pragma unroll
    for (int c = 0; c < 11; c++) {
        const float* wc = sw + c * PD + part * 9;
#pragma unroll
        for (int dd = 0; dd < 9; dd++) a[c] = fmaf(rv[dd], wc[dd], a[c]);
    }
#pragma unroll
    for (int c = 0; c < 11; c++) {
        a[c] += __shfl_down_sync(0xffffffffu, a[c], 1);
        a[c] += __shfl_down_sync(0xffffffffu, a[c], 2);
    }
    if (part == 0) {
        int i = base + row;
        g_QQ[i] = make_ulonglong2(packf2(a[0], a[4]), packf2(a[1], a[5]));
        g_KK[i] = make_ulonglong2(packf2(a[2], a[6]), packf2(a[3], a[7]));
        g_Vop[i] = a[8]; g_Varg[i] = a[9]; g_Vstk[i] = a[10];
    }
}

// ---------------------------------------------------------------------------
// Kernel 1b: generic-D fallback (not used for the benchmark shape).
// ---------------------------------------------------------------------------
__global__ void proj_generic_kernel(
        const float* __restrict__ emb,
        const float* __restrict__ wqp, const float* __restrict__ wkp,
        const float* __restrict__ wvop, const float* __restrict__ wvarg,
        const float* __restrict__ wqs, const float* __restrict__ wks,
        const float* __restrict__ wvs, int T, int D) {
    extern __shared__ float sm[];
    float* sw = sm;
    const int tid = threadIdx.x;
    for (int k = tid; k < 2 * D; k += blockDim.x) {
        sw[k]         = wqp[k];
        sw[2 * D + k] = wkp[k];
        sw[4 * D + k] = wqs[k];
        sw[6 * D + k] = wks[k];
    }
    for (int k = tid; k < D; k += blockDim.x) {
        sw[8 * D + k]  = wvop[k];
        sw[9 * D + k]  = wvarg[k];
        sw[10 * D + k] = wvs[k];
    }
    __syncthreads();
    int i = blockIdx.x * blockDim.x + tid;
    if (i >= T) return;
    const float* e = emb + (size_t)i * D;
    float a[11];
#pragma unroll
    for (int c = 0; c < 11; c++) a[c] = 0.f;
    for (int d = 0; d < D; d++) {
        float ev = e[d];
#pragma unroll
        for (int c = 0; c < 11; c++) a[c] = fmaf(ev, sw[c * D + d], a[c]);
    }
    g_QQ[i] = make_ulonglong2(packf2(a[0], a[4]), packf2(a[1], a[5]));
    g_KK[i] = make_ulonglong2(packf2(a[2], a[6]), packf2(a[3], a[7]));
    g_Vop[i] = a[8]; g_Varg[i] = a[9]; g_Vstk[i] = a[10];
}

// ---------------------------------------------------------------------------
// Kernel 2: per-bin candidate build (unchanged semantics).
// Conservative margin 1.25*Kmax*Delta provably contains the argmax key for
// every query direction mapping to the bin (exact math + fp slack).
// ---------------------------------------------------------------------------
#define BTH 256

__global__ __launch_bounds__(BTH) void build_kernel(int T) {
    __shared__ float red[4][BTH / 32];
    __shared__ float sTP, sTS;
    __shared__ int cP, cS;

    const int b = blockIdx.x;
    const int tid = threadIdx.x, lane = tid & 31, w = tid >> 5;
    const float DLT = 6.2831853071795865f / NB;
    const float th = -3.14159265358979f + (b + 0.5f) * DLT;
    const float ux = cosf(th), uy = sinf(th);
    const unsigned long long ua = packf2(ux, ux), ub = packf2(uy, uy);

    float v[4] = {-FLT_MAX, -FLT_MAX, 0.f, 0.f};  // maxP, maxS, n2P, n2S
#pragma unroll 4
    for (int j = tid; j < T; j += BTH) {
        ulonglong2 kk = g_KK[j];
        unsigned long long s  = fma2(ua, kk.x, mul2(ub, kk.y));
        unsigned long long n2 = fma2(kk.x, kk.x, mul2(kk.y, kk.y));
        v[0] = fmaxf(v[0], lo32(s));  v[1] = fmaxf(v[1], hi32(s));
        v[2] = fmaxf(v[2], lo32(n2)); v[3] = fmaxf(v[3], hi32(n2));
    }
#pragma unroll
    for (int c = 0; c < 4; c++) {
#pragma unroll
        for (int off = 16; off; off >>= 1)
            v[c] = fmaxf(v[c], __shfl_xor_sync(0xffffffffu, v[c], off));
        if (lane == 0) red[c][w] = v[c];
    }
    if (tid == 0) { cP = 0; cS = 0; }
    __syncthreads();
    if (tid == 0) {
        float MP = red[0][0], MS = red[1][0], NP = red[2][0], NS = red[3][0];
#pragma unroll
        for (int k = 1; k < BTH / 32; k++) {
            MP = fmaxf(MP, red[0][k]); MS = fmaxf(MS, red[1][k]);
            NP = fmaxf(NP, red[2][k]); NS = fmaxf(NS, red[3][k]);
        }
        sTP = MP - 1.25f * sqrtf(NP) * DLT;
        sTS = MS - 1.25f * sqrtf(NS) * DLT;
    }
    __syncthreads();
    const float tP = sTP, tS = sTS;

#pragma unroll 4
    for (int j = tid; j < T; j += BTH) {
        ulonglong2 kk = g_KK[j];
        unsigned long long s = fma2(ua, kk.x, mul2(ub, kk.y));
        if (lo32(s) >= tP) { int p = atomicAdd(&cP, 1); if (p < CAP) g_candP[b * CAP + p] = j; }
        if (hi32(s) >= tS) { int p = atomicAdd(&cS, 1); if (p < CAP) g_candS[b * CAP + p] = j; }
    }
    __syncthreads();
    if (tid == 0) { g_cntP[b] = min(cP, CAP); g_cntS[b] = min(cS, CAP); }
}

// ---------------------------------------------------------------------------
// Kernel 3: exact argmax over candidates + gather. TWO threads per query
// (one per head) to halve the dependent-load chain per thread.
// Tie-break (val, then smaller idx) is order-independent and matches
// jnp.argmax first-index semantics.
// ---------------------------------------------------------------------------
__global__ void query_kernel(float* __restrict__ out, int T) {
    const int gidx = blockIdx.x * blockDim.x + threadIdx.x;
    const int i = gidx >> 1;
    const int head = gidx & 1;     // 0 = prog, 1 = stack
    if (i >= T) return;

    ulonglong2 q = g_QQ[i];
    const float qx = head ? hi32(q.x) : lo32(q.x);
    const float qy = head ? hi32(q.y) : lo32(q.y);
    const float SC = NB / 6.2831853071795865f;
    const float PI = 3.14159265358979f;

    int b = (int)((atan2f(qy, qx) + PI) * SC);
    b = min(max(b, 0), NB - 1);

    const int n = head ? g_cntS[b] : g_cntP[b];
    const int* cl = (head ? g_candS : g_candP) + b * CAP;

    float best = -FLT_MAX; int bi = 0x7fffffff;
    for (int t = 0; t < n; t++) {
        int j = cl[t];
        ulonglong2 kk = g_KK[j];
        float kx = head ? hi32(kk.x) : lo32(kk.x);
        float ky = head ? hi32(kk.y) : lo32(kk.y);
        float s = fmaf(qx, kx, __fmul_rn(qy, ky));
        if (s > best || (s == best && j < bi)) { best = s; bi = j; }
    }
    if (head == 0) {
        out[i]     = g_Vop[bi];
        out[T + i] = g_Varg[bi];
    } else {
        out[2 * T + i] = g_Vstk[bi];
    }
}

extern "C" void kernel_launch(void* const* d_in, const int* in_sizes, int n_in,
                              void* d_out, int out_size) {
    const float* emb   = (const float*)d_in[0];
    const float* wqp   = (const float*)d_in[1];
    const float* wkp   = (const float*)d_in[2];
    const float* wvop  = (const float*)d_in[3];
    const float* wvarg = (const float*)d_in[4];
    const float* wqs   = (const float*)d_in[5];
    const float* wks   = (const float*)d_in[6];
    const float* wvs   = (const float*)d_in[7];
    float* out = (float*)d_out;

    const int D = in_sizes[1] / 2;   // WQ_prog is (2, D)
    const int T = in_sizes[0] / D;   // embeddings is (T, D)

    if (D == PD && (T % PR) == 0) {
        proj36_kernel<<<T / PR, PTH>>>(emb, wqp, wkp, wvop, wvarg, wqs, wks, wvs, T);
    } else {
        const int pb = (T + 255) / 256;
        proj_generic_kernel<<<pb, 256, (size_t)(11 * D) * sizeof(float)>>>(
            emb, wqp, wkp, wvop, wvarg, wqs, wks, wvs, T, D);
    }

    build_kernel<<<NB, BTH>>>(T);

    query_kernel<<<(2 * T + 255) / 256, 256>>>(out, T);
}